// round 2
// baseline (speedup 1.0000x reference)
#include <cuda_runtime.h>
#include <cstdint>

// ---------------------------------------------------------------------------
// TripletLoss with JAX-exact gumbel sampling (threefry2x32, key(42)).
//
// B=384, D=256, C=48, epoch=5 (>3 path). The (B,B,B) gumbel tensor is only
// consumed at ~1.3K valid (anchor,positive) pairs x 384 candidates, and the
// gumbel only matters where the semi-hard mask is true -> evaluate threefry
// on demand instead of materializing 56.6M elements.
//
// RNG: JAX partitionable threefry (default since 0.4.36). For 32-bit draws
// the random word is XOR of the two threefry output words:
//   bits = x0_out ^ x1_out, counter = (flat_idx >> 32, flat_idx & 0xffffffff)
// ---------------------------------------------------------------------------

#define B 384
#define D 256
#define NPAIR_MAX ((B * (B - 1)) / 2)
#define MARGIN 0.2f
#define TINYF 1.17549435e-38f

// 0 = partitionable (x0 ^ x1)   <- JAX default, believed correct
// 1 = partitionable, x0 only    (previous attempt: rel_err 3.5e-3)
// 2 = legacy split-iota
#define RNG_VARIANT 0

// ---- scratch (device globals; no allocation allowed) ----------------------
__device__ float g_fT[D * B];       // transposed features, coalesced by j
__device__ float g_dist[B * B];
__device__ float g_nlogd[B * B];    // -log(dist)
__device__ int   g_pairs[NPAIR_MAX];
__device__ int   g_npairs;
__device__ float g_total;
__device__ int   g_count;

// ---- threefry2x32, JAX schedule, key = [0, 42] -----------------------------
__device__ __forceinline__ uint32_t rotl32(uint32_t x, int d) {
    return __funnelshift_l(x, x, d);
}

__device__ __forceinline__ void threefry2x32(uint32_t x0, uint32_t x1,
                                             uint32_t& o0, uint32_t& o1) {
    const uint32_t k0 = 0u, k1 = 42u;
    const uint32_t k2 = k0 ^ k1 ^ 0x1BD11BDAu;
    x0 += k0; x1 += k1;
#define TF_RND(r) { x0 += x1; x1 = rotl32(x1, (r)); x1 ^= x0; }
    TF_RND(13) TF_RND(15) TF_RND(26) TF_RND(6)
    x0 += k1; x1 += k2 + 1u;
    TF_RND(17) TF_RND(29) TF_RND(16) TF_RND(24)
    x0 += k2; x1 += k0 + 2u;
    TF_RND(13) TF_RND(15) TF_RND(26) TF_RND(6)
    x0 += k0; x1 += k1 + 3u;
    TF_RND(17) TF_RND(29) TF_RND(16) TF_RND(24)
    x0 += k1; x1 += k2 + 4u;
    TF_RND(13) TF_RND(15) TF_RND(26) TF_RND(6)
    x0 += k2; x1 += k0 + 5u;
#undef TF_RND
    o0 = x0; o1 = x1;
}

// gumbel value at flat index n of the (B,B,B) tensor, matching
// jax.random.gumbel(jax.random.key(42), (B,B,B), float32)
__device__ __forceinline__ float gumbel_at(uint64_t n) {
    uint32_t bits;
#if RNG_VARIANT == 0
    {
        uint32_t o0, o1;
        threefry2x32((uint32_t)(n >> 32), (uint32_t)n, o0, o1);
        bits = o0 ^ o1;   // JAX partitionable 32-bit draw: xor of output words
    }
#elif RNG_VARIANT == 1
    {
        uint32_t o0, o1;
        threefry2x32((uint32_t)(n >> 32), (uint32_t)n, o0, o1);
        bits = o0;
    }
#else
    {
        const uint64_t half = (uint64_t)B * B * B / 2;  // B^3 is even
        uint32_t o0, o1;
        if (n < half) {
            threefry2x32((uint32_t)n, (uint32_t)(n + half), o0, o1);
            bits = o0;
        } else {
            threefry2x32((uint32_t)(n - half), (uint32_t)n, o0, o1);
            bits = o1;
        }
    }
#endif
    // uniform in [tiny, 1): mantissa bits with exponent of 1.0, minus 1
    float f = __uint_as_float((bits >> 9) | 0x3f800000u) - 1.0f;
    // f * (1 - tiny) + tiny, with (1 - tiny) == 1.0f in fp32; clamp at tiny
    float u = fmaxf(TINYF, f + TINYF);
    return -logf(-logf(u));
}

// ---- kernels ---------------------------------------------------------------
__global__ void k_init() {
    g_npairs = 0;
    g_total = 0.0f;
    g_count = 0;
}

__global__ void k_transpose(const float* __restrict__ f) {
    int idx = blockIdx.x * blockDim.x + threadIdx.x;
    if (idx < B * D) {
        int j = idx / D, d = idx % D;
        g_fT[d * B + j] = f[idx];
    }
}

__global__ void k_dist(const float* __restrict__ f) {
    __shared__ float fi[D];
    int i = blockIdx.x;
    int t = threadIdx.x;
    if (t < D) fi[t] = f[i * D + t];
    __syncthreads();
    int j = t;  // blockDim == B
    float s0 = 0.f, s1 = 0.f, s2 = 0.f, s3 = 0.f;
#pragma unroll 4
    for (int d = 0; d < D; d += 4) {
        float d0 = fi[d + 0] - g_fT[(d + 0) * B + j];
        float d1 = fi[d + 1] - g_fT[(d + 1) * B + j];
        float d2 = fi[d + 2] - g_fT[(d + 2) * B + j];
        float d3 = fi[d + 3] - g_fT[(d + 3) * B + j];
        s0 += d0 * d0; s1 += d1 * d1; s2 += d2 * d2; s3 += d3 * d3;
    }
    float s = (s0 + s1) + (s2 + s3);
    s = fmaxf(s, 1e-11f);           // jnp.clip(x, 1e-11)
    float dd = sqrtf(s);
    g_dist[i * B + j] = dd;
    g_nlogd[i * B + j] = -logf(dd);
}

__global__ void k_pairs(const int* __restrict__ labels) {
    int i = blockIdx.x, p = threadIdx.x;
    if (p > i && labels[p] == labels[i]) {
        int idx = atomicAdd(&g_npairs, 1);
        g_pairs[idx] = i * B + p;
    }
}

// One block per (anchor, positive) pair; 384 threads cover all candidates k.
__global__ void k_pair_work(const int* __restrict__ labels,
                            const int* __restrict__ epoch) {
    const bool semi_mode = (epoch[0] > 3);
    __shared__ float s_val[12];
    __shared__ int   s_idx[12];
    __shared__ int   s_any[12];
    const int t = threadIdx.x;
    const int lane = t & 31, w = t >> 5;

    for (int pi = blockIdx.x; pi < g_npairs; pi += gridDim.x) {
        int code = g_pairs[pi];
        int i = code / B, p = code % B;
        int li = labels[i];
        float dpos = g_dist[i * B + p];

        int k = t;
        bool neg = (labels[k] != li);
        float dik = g_dist[i * B + k];
        bool semi = semi_mode ? (neg && (dik > dpos) && (dik < dpos + MARGIN))
                              : neg;
        float score = -3.0e38f;
        if (semi) {
            float base = semi_mode ? g_nlogd[i * B + k] : 0.0f;
            score = base + gumbel_at(((uint64_t)i * B + p) * B + k);
        }
        int ix = k;

        // warp argmax, first-index tie break (matches jnp.argmax)
#pragma unroll
        for (int off = 16; off; off >>= 1) {
            float ov = __shfl_down_sync(0xffffffffu, score, off);
            int   oi = __shfl_down_sync(0xffffffffu, ix, off);
            if (ov > score || (ov == score && oi < ix)) { score = ov; ix = oi; }
        }
        unsigned anyw = __ballot_sync(0xffffffffu, semi);
        if (lane == 0) { s_val[w] = score; s_idx[w] = ix; s_any[w] = (anyw != 0); }
        __syncthreads();

        if (t == 0) {
            float bv = s_val[0]; int bi = s_idx[0]; bool any = (s_any[0] != 0);
#pragma unroll
            for (int ww = 1; ww < 12; ww++) {
                if (s_any[ww]) any = true;
                if (s_val[ww] > bv || (s_val[ww] == bv && s_idx[ww] < bi)) {
                    bv = s_val[ww]; bi = s_idx[ww];
                }
            }
            if (any) {
                float per = fmaxf(dpos - g_dist[i * B + bi] + MARGIN, 0.0f);
                atomicAdd(&g_total, per);
                atomicAdd(&g_count, 1);
            }
        }
        __syncthreads();
    }
}

__global__ void k_final(float* __restrict__ out) {
    int c = g_count;
    out[0] = (c > 0) ? (g_total / (float)c) : 0.0f;
}

// ---- launch ----------------------------------------------------------------
extern "C" void kernel_launch(void* const* d_in, const int* in_sizes, int n_in,
                              void* d_out, int out_size) {
    const float* feat   = (const float*)d_in[0];
    const int*   labels = (const int*)d_in[1];
    const int*   epoch  = (const int*)d_in[2];
    float* out = (float*)d_out;

    k_init<<<1, 1>>>();
    k_transpose<<<(B * D + 255) / 256, 256>>>(feat);
    k_dist<<<B, B>>>(feat);
    k_pairs<<<B, B>>>(labels);
    k_pair_work<<<1536, B>>>(labels, epoch);
    k_final<<<1, 1>>>(out);
}